// round 10
// baseline (speedup 1.0000x reference)
#include <cuda_runtime.h>
#include <math.h>

#define BN 32     // B*C images
#define HH 256
#define WW 256
#define TILE 16   // output rows per col-pass block
#define FG_INF 1e6f
#define BIGF   3.0e38f   // padding: r2 + BIGF never wins, no overflow

// scratch: squared row-distance (sign bit = "input was NaN"), 8 MB, L2-resident
__device__ float g_g2[BN * HH * WW];

__device__ __forceinline__ float sqrt_approx(float x) {
    float y;
    asm("sqrt.approx.f32 %0, %1;" : "=f"(y) : "f"(x));
    return y;
}

// exact per-pixel row distance recompute from x (cold path, ~never taken)
__device__ __forceinline__ float row_g_global(const float* __restrict__ xrow, int j) {
    if (xrow[j] == 0.0f) return 0.0f;
    int dl = 1 << 30, dr = 1 << 30;
    for (int t = j - 1; t >= 0; --t) if (xrow[t] == 0.0f) { dl = j - t; break; }
    for (int t = j + 1; t < WW; ++t) if (xrow[t] == 0.0f) { dr = t - j; break; }
    int d = min(dl, dr);
    if (d >= (1 << 30)) return FG_INF + fminf((float)(j + 1), (float)(WW - j));
    return (float)d;
}

// ---------------------------------------------------------------------------
// Pass A: row distances, warp-per-row, branch-free funnel windows.
// Every row computed exactly once (no halo redundancy).
// ---------------------------------------------------------------------------
__global__ void __launch_bounds__(512)
row_pass(const float* __restrict__ x) {
    const int b   = threadIdx.x & 31;          // lane
    const int row = blockIdx.x * 16 + (threadIdx.x >> 5);   // [0, BN*HH)
    const float* __restrict__ xr = x + row * WW;

    unsigned mm[10];                           // bg mask words, zero-padded ends
    unsigned nn8 = 0u;                         // bit k = isnan(pixel b+32k)
    mm[0] = 0u; mm[9] = 0u;
    #pragma unroll
    for (int k = 0; k < 8; ++k) {
        const float xv = xr[b + 32 * k];
        mm[k + 1] = __ballot_sync(0xFFFFFFFFu, xv == 0.0f);  // NaN -> fg
        nn8 |= ((unsigned)isnan(xv)) << k;
    }

    unsigned cold = 0u;
    #pragma unroll
    for (int k = 0; k < 8; ++k) {
        // self-inclusive windows: R bit t = pixel j+t, L bit (31-t) = pixel j-t
        const unsigned R = __funnelshift_rc(mm[k + 1], mm[k + 2], b);
        const unsigned L = __funnelshift_lc(mm[k], mm[k + 1], 31 - b);
        const int dr = R ? (__ffs(R) - 1) : 1000;
        const int dl = L ? __clz(L) : 1000;
        const int d = min(dr, dl);
        cold |= ((unsigned)(d >= 1000)) << k;
        float s2 = (float)(d * d);
        // inject NaN flag into sign bit (fg => d>=1, bg never NaN)
        s2 = __uint_as_float(__float_as_uint(s2) | (((nn8 >> k) & 1u) << 31));
        g_g2[row * WW + b + 32 * k] = s2;
    }
    if (__any_sync(0xFFFFFFFFu, cold != 0u)) {   // ~never taken
        #pragma unroll 1
        for (int k = 0; k < 8; ++k) if ((cold >> k) & 1u) {
            const int j = b + 32 * k;
            const float g = row_g_global(xr, j);
            float s2 = g * g;
            s2 = __uint_as_float(__float_as_uint(s2) | (((nn8 >> k) & 1u) << 31));
            g_g2[row * WW + j] = s2;
        }
    }
}

// ---------------------------------------------------------------------------
// Pass B: column lower-envelope, branch-free r<=3 window + ballot-guarded
// exact tail. g2 reads are coalesced and L2-resident.
// ---------------------------------------------------------------------------
__global__ void __launch_bounds__(512)
col_pass(const float* __restrict__ x, float* __restrict__ out) {
    const int n   = blockIdx.y;                // image
    const int i0  = blockIdx.x * TILE;         // first output row of block
    const int j   = threadIdx.x & (WW - 1);    // column
    const int lo0 = (threadIdx.x >> 8) * 8;    // 0 or 8: first of 8 output rows
    const int ib  = i0 + lo0;                  // first output row of thread
    const float* __restrict__ g2 = g_g2 + n * (HH * WW) + j;

    float v[14];                               // rows ib-3 .. ib+10 (clamped)
    #pragma unroll
    for (int t = 0; t < 14; ++t) {
        const int r = ib - 3 + t;
        v[t] = (r >= 0 && r < HH) ? g2[r * WW] : BIGF;
    }

    unsigned need = 0u;
    #pragma unroll
    for (int p = 0; p < 8; ++p) {
        const int c = 3 + p;
        const bool nanp = signbit(v[c]);
        float best = fabsf(v[c]);
        #pragma unroll
        for (int r = 1; r <= 3; ++r) {
            const float r2 = (float)(r * r);
            best = fminf(best, r2 + fabsf(v[c - r]));
            best = fminf(best, r2 + fabsf(v[c + r]));
        }
        need |= ((unsigned)(best > 16.0f)) << p;
        const float d = sqrt_approx(best);
        out[(n * HH + ib + p) * WW + j] =
            nanp ? __int_as_float(0x7FC00000) : d;
    }

    // exact tail, warp-uniform guard, rare (needs d^2 > 16)
    if (__any_sync(0xFFFFFFFFu, need != 0u)) {
        #pragma unroll 1
        for (int p = 0; p < 8; ++p) if ((need >> p) & 1u) {
            const int i = ib + p;
            const bool nanp = signbit(g2[i * WW]);
            float best = fabsf(g2[i * WW]);
            for (int r = 1; r < HH; ++r) {
                const float r2 = (float)(r * r);
                if (r2 >= best) break;
                const int up = i - r, dn = i + r;
                if (up >= 0) best = fminf(best, r2 + fabsf(g2[up * WW]));
                if (dn < HH) best = fminf(best, r2 + fabsf(g2[dn * WW]));
            }
            out[(n * HH + i) * WW + j] =
                nanp ? __int_as_float(0x7FC00000) : sqrt_approx(best);
        }
    }
}

extern "C" void kernel_launch(void* const* d_in, const int* in_sizes, int n_in,
                              void* d_out, int out_size) {
    const float* x = (const float*)d_in[0];
    float* out = (float*)d_out;

    row_pass<<<BN * HH / 16, 512>>>(x);
    col_pass<<<dim3(HH / TILE, BN), 512>>>(x, out);
}

// round 11
// speedup vs baseline: 1.1866x; 1.1866x over previous
#include <cuda_runtime.h>
#include <math.h>

#define BN 32     // B*C images
#define HH 256
#define WW 256
#define TILE 16   // output rows per block
#define HALO 4    // shared halo rows each side (r<=4 tail in shared; exact)
#define SROWS (TILE + 2*HALO)   // 24
#define FG_INF 1e6f
#define BIGF   3.0e38f          // padding: r2 + BIGF never wins, no overflow

__device__ __forceinline__ float sqrt_approx(float x) {
    float y;
    asm("sqrt.approx.f32 %0, %1;" : "=f"(y) : "f"(x));
    return y;
}

// exact per-pixel row distance recompute from x (cold path, ~never taken)
__device__ __forceinline__ float row_g_global(const float* __restrict__ xrow, int j) {
    if (xrow[j] == 0.0f) return 0.0f;
    int dl = 1 << 30, dr = 1 << 30;
    for (int t = j - 1; t >= 0; --t) if (xrow[t] == 0.0f) { dl = j - t; break; }
    for (int t = j + 1; t < WW; ++t) if (xrow[t] == 0.0f) { dr = t - j; break; }
    int d = min(dl, dr);
    if (d >= (1 << 30)) return FG_INF + fminf((float)(j + 1), (float)(WW - j));
    return (float)d;
}

__global__ void __launch_bounds__(256, 5)
edt_fused(const float* __restrict__ x, float* __restrict__ out) {
    __shared__ float g2s[SROWS][WW];   // 24 KB; sign bit = "input was NaN"

    const int n  = blockIdx.y;                 // image
    const int i0 = blockIdx.x * TILE;          // first output row
    const int rowbase = i0 - HALO;             // global row of shared row 0
    const int b    = threadIdx.x & 31;         // lane
    const int wrp  = threadIdx.x >> 5;         // 0..7

    // --- Phase 1: row distances (warp-per-row, branch-free funnel windows) ---
    #pragma unroll
    for (int pass = 0; pass < 3; ++pass) {
        const int lr = wrp + pass * 8;         // local shared row 0..23
        const int gr = rowbase + lr;           // global row
        if (gr < 0 || gr >= HH) {
            #pragma unroll
            for (int k = 0; k < 8; ++k) g2s[lr][b + 32 * k] = BIGF;
            continue;
        }
        const float* __restrict__ xr = x + (n * HH + gr) * WW;

        unsigned mm[10];                       // bg mask words, zero-padded ends
        unsigned nn8 = 0u;                     // bit k = isnan(pixel b+32k)
        mm[0] = 0u; mm[9] = 0u;
        #pragma unroll
        for (int k = 0; k < 8; ++k) {
            const float xv = xr[b + 32 * k];
            mm[k + 1] = __ballot_sync(0xFFFFFFFFu, xv == 0.0f);  // NaN -> fg
            nn8 |= ((unsigned)isnan(xv)) << k;
        }

        unsigned cold = 0u;
        #pragma unroll
        for (int k = 0; k < 8; ++k) {
            // self-inclusive windows: R bit t = pixel j+t, L bit (31-t) = pixel j-t
            const unsigned R = __funnelshift_rc(mm[k + 1], mm[k + 2], b);
            const unsigned L = __funnelshift_lc(mm[k], mm[k + 1], 31 - b);
            const int dr = R ? (__ffs(R) - 1) : 1000;
            const int dl = L ? __clz(L) : 1000;
            const int d = min(dr, dl);
            cold |= ((unsigned)(d >= 1000)) << k;
            float s2 = (float)(d * d);
            // inject NaN flag into sign bit (fg => d>=1, bg never NaN)
            s2 = __uint_as_float(__float_as_uint(s2) |
                                 (((nn8 >> k) & 1u) << 31));
            g2s[lr][b + 32 * k] = s2;
        }
        if (__any_sync(0xFFFFFFFFu, cold != 0u)) {   // ~never taken
            #pragma unroll 1
            for (int k = 0; k < 8; ++k) if ((cold >> k) & 1u) {
                const int j = b + 32 * k;
                const float g = row_g_global(xr, j);
                float s2 = g * g;
                s2 = __uint_as_float(__float_as_uint(s2) |
                                     (((nn8 >> k) & 1u) << 31));
                g2s[lr][j] = s2;
            }
        }
    }
    __syncthreads();

    // --- Phase 2: column lower-envelope, branch-free r<=3 window, ballot tail ---
    const int j = threadIdx.x;                 // column (0..255)

    #pragma unroll
    for (int sub = 0; sub < 2; ++sub) {
        const int lo0 = sub * 8;               // first of 8 local output rows

        float v[14];                           // shared rows HALO+lo0-3 .. +10
        #pragma unroll
        for (int t = 0; t < 14; ++t)
            v[t] = g2s[HALO + lo0 - 3 + t][j];

        unsigned need = 0u;
        #pragma unroll
        for (int p = 0; p < 8; ++p) {
            const int c = 3 + p;
            const bool nanp = signbit(v[c]);
            float best = fabsf(v[c]);
            #pragma unroll
            for (int r = 1; r <= 3; ++r) {
                const float r2 = (float)(r * r);
                best = fminf(best, r2 + fabsf(v[c - r]));
                best = fminf(best, r2 + fabsf(v[c + r]));
            }
            need |= ((unsigned)(best > 16.0f)) << p;
            const float d = sqrt_approx(best);
            out[(n * HH + i0 + lo0 + p) * WW + j] =
                nanp ? __int_as_float(0x7FC00000) : d;
        }

        // exact tail, warp-uniform guard, ~never taken (needs d^2 > 16)
        if (__any_sync(0xFFFFFFFFu, need != 0u)) {
            #pragma unroll 1
            for (int p = 0; p < 8; ++p) if ((need >> p) & 1u) {
                const int s = HALO + lo0 + p;  // this pixel's shared row
                const bool nanp = signbit(g2s[s][j]);
                float best = fabsf(g2s[s][j]);
                // shared tail: r = 4 only (s-4 >= 0, s+4 <= SROWS-1 by layout)
                best = fminf(best, 16.0f + fabsf(g2s[s - 4][j]));
                best = fminf(best, 16.0f + fabsf(g2s[s + 4][j]));
                // exact global fallback
                if (25.0f < best) {
                    const int i = i0 + lo0 + p;
                    for (int r = 5; r < HH; ++r) {
                        const float r2 = (float)(r * r);
                        if (r2 >= best) break;
                        const int up = i - r, dn = i + r;
                        if (up >= 0) {
                            const float g = row_g_global(x + (n * HH + up) * WW, j);
                            best = fminf(best, r2 + g * g);
                        }
                        if (dn < HH) {
                            const float g = row_g_global(x + (n * HH + dn) * WW, j);
                            best = fminf(best, r2 + g * g);
                        }
                    }
                }
                out[(n * HH + i0 + lo0 + p) * WW + j] =
                    nanp ? __int_as_float(0x7FC00000) : sqrt_approx(best);
            }
        }
    }
}

extern "C" void kernel_launch(void* const* d_in, const int* in_sizes, int n_in,
                              void* d_out, int out_size) {
    const float* x = (const float*)d_in[0];
    float* out = (float*)d_out;
    edt_fused<<<dim3(HH / TILE, BN), 256>>>(x, out);
}